// round 15
// baseline (speedup 1.0000x reference)
#include <cuda_runtime.h>
#include <cuda_fp16.h>
#include <cstdint>

// ---------------------------------------------------------------------------
// SampleAndAggregate (GraphSAGE, 2-layer maxpool)
// Round 15: H/T GEMMs reworked to 64x64 warp tiles (BM=128, BN=256, occ 1)
//           to cut ldmatrix traffic per MMA (L1 pipe was the R14 bottleneck).
// ---------------------------------------------------------------------------

#define BATCH 512
#define FEAT  256
#define HIDW  512
#define DOUT  128
#define DEG   128
#define NN    100000
#define NS_A  25
#define NS_B  10
#define N1    (BATCH*NS_B)     // 5120
#define N2    (N1*NS_A)        // 128000

// ------------------------- scratch (device globals) ------------------------
__device__ int    g_s1[2*N1];
__device__ int    g_s2[2*N2];
__device__ int    g_b12[2*BATCH];
__device__ __half g_featH[(size_t)NN*FEAT];
__device__ __half g_Wp0t[HIDW*FEAT];   // [512][256]
__device__ __half g_Wn0t[DOUT*HIDW];   // [128][512]
__device__ __half g_Ws0t[DOUT*FEAT];   // [128][256]
__device__ __half g_Wp1t[HIDW*2*DOUT]; // [512][256]
__device__ __half g_H[(size_t)NN*HIDW];
__device__ __half g_pool1[2*(size_t)N1*HIDW];
__device__ __half g_pool0[2*(size_t)BATCH*HIDW];
__device__ __half g_y1[2*(size_t)N1*2*DOUT];
__device__ float  g_y0[2*(size_t)BATCH*2*DOUT];
__device__ float  g_T[2*(size_t)N1*HIDW];
__device__ float  g_pool2[2*(size_t)BATCH*HIDW];

// ------------------------------- sampling ----------------------------------
__global__ void k_sample1(const int* __restrict__ b1, const int* __restrict__ b2,
                          const int* __restrict__ adj) {
    int i = blockIdx.x * blockDim.x + threadIdx.x;
    if (i >= 2 * N1) return;
    int t = i / N1, r = i % N1;
    int n = r / NS_B, j = r % NS_B;
    int node = (t ? b2 : b1)[n];
    if (j == 0) g_b12[t * BATCH + n] = node;
    g_s1[t * N1 + r] = adj[(size_t)node * DEG + j];
}
__global__ void k_sample2(const int* __restrict__ adj) {
    int i = blockIdx.x * blockDim.x + threadIdx.x;
    if (i >= 2 * N2) return;
    int t = i / N2, r = i % N2;
    int n = r / NS_A, j = r % NS_A;
    int parent = g_s1[t * N1 + n];
    g_s2[t * N2 + r] = adj[(size_t)parent * DEG + j];
}

// ----- merged prep: weight transpose+cvt (blocks 0..351) + feat cvt rest ----
__global__ void k_prep(const float* __restrict__ Wp0, const float* __restrict__ Wn0,
                       const float* __restrict__ Ws0, const float* __restrict__ Wp1,
                       const float* __restrict__ feat) {
    int b = blockIdx.x;
    int tid = threadIdx.x;
    if (b < 352) {
        __shared__ float t[32][33];
        int tx = tid & 31, ty = tid >> 5;
        const float* W; __half* out; int K, N;
        if (b < 128)      { W = Wp0; out = g_Wp0t; K = 256; N = 512; }
        else if (b < 192) { b -= 128; W = Wn0; out = g_Wn0t; K = 512; N = 128; }
        else if (b < 224) { b -= 192; W = Ws0; out = g_Ws0t; K = 256; N = 128; }
        else              { b -= 224; W = Wp1; out = g_Wp1t; K = 256; N = 512; }
        int tilesN = N / 32;
        int n0 = (b % tilesN) * 32, k0 = (b / tilesN) * 32;
        for (int i = ty; i < 32; i += 8)
            t[i][tx] = W[(size_t)(k0 + i) * N + n0 + tx];
        __syncthreads();
        for (int i = ty; i < 32; i += 8)
            out[(size_t)(n0 + i) * K + k0 + tx] = __float2half_rn(t[tx][i]);
    } else {
        size_t i = (size_t)(b - 352) * 256 + tid;
        const float4* src = (const float4*)feat + i * 2;
        float4 a = src[0], c = src[1];
        __half2 h[4] = { __floats2half2_rn(a.x, a.y), __floats2half2_rn(a.z, a.w),
                         __floats2half2_rn(c.x, c.y), __floats2half2_rn(c.z, c.w) };
        *((uint4*)g_featH + i) = *(uint4*)h;
    }
}

// ----------------------------- fp16 MMA helpers -----------------------------
__device__ __forceinline__ void mma_f16(float c[4], uint32_t a0, uint32_t a1,
                                        uint32_t a2, uint32_t a3,
                                        uint32_t b0, uint32_t b1) {
    asm volatile(
        "mma.sync.aligned.m16n8k16.row.col.f32.f16.f16.f32 "
        "{%0,%1,%2,%3}, {%4,%5,%6,%7}, {%8,%9}, {%0,%1,%2,%3};"
        : "+f"(c[0]), "+f"(c[1]), "+f"(c[2]), "+f"(c[3])
        : "r"(a0), "r"(a1), "r"(a2), "r"(a3), "r"(b0), "r"(b1));
}
__device__ __forceinline__ void ldsm_x4(uint32_t& r0, uint32_t& r1,
                                        uint32_t& r2, uint32_t& r3,
                                        uint32_t addr) {
    asm volatile("ldmatrix.sync.aligned.m8n8.x4.shared.b16 {%0,%1,%2,%3}, [%4];"
                 : "=r"(r0), "=r"(r1), "=r"(r2), "=r"(r3) : "r"(addr));
}
__device__ __forceinline__ void cp16(uint32_t dst, const void* src, uint32_t sz) {
    asm volatile("cp.async.cg.shared.global [%0], [%1], 16, %2;"
                 :: "r"(dst), "l"(src), "r"(sz) : "memory");
}
#define CP_COMMIT() asm volatile("cp.async.commit_group;" ::: "memory")
#define CP_WAIT(n)  asm volatile("cp.async.wait_group %0;" :: "n"(n) : "memory")

// ---------------------------------------------------------------------------
// Wide-tile B-resident GEMM: BM=128, BN=256, KT=256, warp tile 64x64,
// 8 warps (2m x 4n), occupancy 1.  B slice (256 x 256 fp16) resident in SMEM.
// C = relu(A @ Bt^T + bias); OUTH selects fp16/fp32 output.
// ---------------------------------------------------------------------------
template<bool OUTH>
__global__ __launch_bounds__(256, 1)
void k_gemm_w64(const __half* __restrict__ A, int M,
                const __half* __restrict__ Bt,
                const float* __restrict__ bias,
                void* __restrict__ Cv, int ldc)
{
    constexpr int BM = 128, BK = 32, KT = 256, BN = 256, STG = 4;
    constexpr int LDA = BK + 8;            // 40 halves / A row
    constexpr int LDB = KT + 8;            // 264 halves / B row
    constexpr int ktiles = KT / BK;        // 8
    constexpr uint32_t ABUF = BM * LDA * 2;
    extern __shared__ __align__(16) __half sm[];

    const int tid  = threadIdx.x;
    const int lane = tid & 31;
    const int warp = tid >> 5;
    const int wm = warp >> 2;              // 0..1  (64-row half)
    const int wn = warp & 3;               // 0..3  (64-col quarter)
    const int m0g = blockIdx.x * BM;
    const int n0g = blockIdx.y * BN;

    const uint32_t b_base = (uint32_t)__cvta_generic_to_shared(sm);
    const uint32_t a_base = b_base + BN * LDB * 2;

    // ---- load this CTA's B slice (256 x 256 fp16) once ----
    constexpr int BCH = BN * (KT / 8) / 256;       // 32 chunks / thread
#pragma unroll
    for (int i = 0; i < BCH; i++) {
        int f = tid + i * 256;
        int row = f / (KT / 8), u = f % (KT / 8);
        cp16(b_base + (row * LDB + u * 8) * 2,
             Bt + (size_t)(n0g + row) * KT + u * 8, 16u);
    }
    CP_COMMIT();

    float acc[4][8][4];
#pragma unroll
    for (int i = 0; i < 4; i++)
#pragma unroll
        for (int j = 0; j < 8; j++)
#pragma unroll
            for (int r = 0; r < 4; r++) acc[i][j][r] = 0.f;

    auto load_A = [&](int s, int kk) {
#pragma unroll
        for (int i = 0; i < 2; i++) {
            int f = tid + i * 256;
            int m = f >> 2, u = f & 3;
            int row = m0g + m;
            bool v = row < M;
            const __half* src = A;
            if (v) src = A + (size_t)row * KT + kk + u * 8;
            cp16(a_base + s * ABUF + (m * LDA + u * 8) * 2, src, v ? 16u : 0u);
        }
        CP_COMMIT();
    };

    const int m_base = wm * 64, n_base = wn * 64;
    const int rql = lane >> 2, cql = lane & 3;

    uint32_t aoff[4], boff[4];
#pragma unroll
    for (int mt = 0; mt < 4; mt++)
        aoff[mt] = ((m_base + mt * 16 + (lane & 15)) * LDA + (lane >> 4) * 8) * 2;
#pragma unroll
    for (int p = 0; p < 4; p++) {
        int rowb = n_base + p * 16 + ((lane >> 4) & 1) * 8 + (lane & 7);
        boff[p] = (rowb * LDB + ((lane >> 3) & 1) * 8) * 2;
    }

    load_A(0, 0);
    load_A(1, BK);
    load_A(2, 2 * BK);

    for (int kt = 0; kt < ktiles; kt++) {
        const int rem = ktiles - 1 - kt;
        if (rem >= 2) CP_WAIT(2);
        else if (rem == 1) CP_WAIT(1);
        else CP_WAIT(0);
        __syncthreads();
        if (kt + 3 < ktiles) load_A((kt + 3) % STG, (kt + 3) * BK);

        const int s = kt % STG;
#pragma unroll
        for (int k0 = 0; k0 < BK; k0 += 16) {
            uint32_t af[4][4], bf[8][2];
            const uint32_t ab = a_base + s * ABUF + k0 * 2;
            const uint32_t bb = b_base + (kt * BK + k0) * 2;
#pragma unroll
            for (int mt = 0; mt < 4; mt++)
                ldsm_x4(af[mt][0], af[mt][1], af[mt][2], af[mt][3], ab + aoff[mt]);
#pragma unroll
            for (int p = 0; p < 4; p++)
                ldsm_x4(bf[2 * p][0], bf[2 * p][1], bf[2 * p + 1][0],
                        bf[2 * p + 1][1], bb + boff[p]);
#pragma unroll
            for (int mt = 0; mt < 4; mt++)
#pragma unroll
                for (int nt = 0; nt < 8; nt++)
                    mma_f16(acc[mt][nt], af[mt][0], af[mt][1], af[mt][2],
                            af[mt][3], bf[nt][0], bf[nt][1]);
        }
    }

    // epilogue: bias + relu, fp16 or fp32 out
#pragma unroll
    for (int mt = 0; mt < 4; mt++) {
#pragma unroll
        for (int half = 0; half < 2; half++) {
            int row = m0g + m_base + mt * 16 + rql + half * 8;
            if (row >= M) continue;
#pragma unroll
            for (int nt = 0; nt < 8; nt++) {
                int col = n0g + n_base + nt * 8 + cql * 2;
                float2 v;
                v.x = fmaxf(acc[mt][nt][half * 2 + 0] + bias[col],     0.f);
                v.y = fmaxf(acc[mt][nt][half * 2 + 1] + bias[col + 1], 0.f);
                if (OUTH) {
                    *(__half2*)((__half*)Cv + (size_t)row * ldc + col) =
                        __floats2half2_rn(v.x, v.y);
                } else {
                    *(float2*)((float*)Cv + (size_t)row * ldc + col) = v;
                }
            }
        }
    }
}

// ---------------------------------------------------------------------------
// Merged layer-0 GEMM: all four combine GEMMs in one launch (176 CTAs).
// (unchanged from R14 — N=128 outputs can't use the wide tile)
// ---------------------------------------------------------------------------
__global__ __launch_bounds__(256, 1)
void k_gemm_l0(const __half* __restrict__ featH, const int* __restrict__ s1,
               const __half* __restrict__ pool1, const int* __restrict__ b12,
               const __half* __restrict__ pool0,
               const __half* __restrict__ Ws0t, const __half* __restrict__ Wn0t,
               __half* __restrict__ y1, float* __restrict__ y0)
{
    constexpr int BM = 128, BK = 32, STG = 4;
    constexpr int LDA = BK + 8;
    constexpr uint32_t ABUF = BM * LDA * 2;
    extern __shared__ __align__(16) __half sm[];

    int b = blockIdx.x;
    const __half* A; const int* gidx = nullptr; const __half* Bt;
    int M, KT; bool outh;
    __half* Ch = nullptr; float* Cf = nullptr;
    if (b < 80)       { A = featH; gidx = s1;  Bt = Ws0t; M = 2*N1;    KT = 256; outh = true;  Ch = y1; }
    else if (b < 160) { b -= 80;  A = pool1;             Bt = Wn0t; M = 2*N1;    KT = 512; outh = true;  Ch = y1 + 128; }
    else if (b < 168) { b -= 160; A = featH; gidx = b12; Bt = Ws0t; M = 2*BATCH; KT = 256; outh = false; Cf = y0; }
    else              { b -= 168; A = pool0;             Bt = Wn0t; M = 2*BATCH; KT = 512; outh = false; Cf = y0 + 128; }
    const int ldc = 256;
    const int m0g = b * BM;
    const int LDB = KT + 8;
    const int ktiles = KT / BK;
    const int kt8 = KT / 8;

    const int tid  = threadIdx.x;
    const int lane = tid & 31;
    const int warp = tid >> 5;
    const int wm = warp >> 2, wn = warp & 3;

    const uint32_t b_base = (uint32_t)__cvta_generic_to_shared(sm);
    const uint32_t a_base = b_base + 128 * (512 + 8) * 2;

    const int bch = 128 * kt8 / 256;
    for (int i = 0; i < bch; i++) {
        int f = tid + i * 256;
        int row = f / kt8, u = f % kt8;
        cp16(b_base + (row * LDB + u * 8) * 2,
             Bt + (size_t)row * KT + u * 8, 16u);
    }
    CP_COMMIT();

    float acc[4][4][4];
#pragma unroll
    for (int i = 0; i < 4; i++)
#pragma unroll
        for (int j = 0; j < 4; j++)
#pragma unroll
            for (int r = 0; r < 4; r++) acc[i][j][r] = 0.f;

    auto load_A = [&](int s, int kk) {
#pragma unroll
        for (int i = 0; i < 2; i++) {
            int f = tid + i * 256;
            int m = f >> 2, u = f & 3;
            int row = m0g + m;
            bool v = row < M;
            const __half* src = A;
            if (v) {
                int r = gidx ? gidx[row] : row;
                src = A + (size_t)r * KT + kk + u * 8;
            }
            cp16(a_base + s * ABUF + (m * LDA + u * 8) * 2, src, v ? 16u : 0u);
        }
        CP_COMMIT();
    };

    const int m_base = wm * 64, n_base = wn * 32;
    const int rql = lane >> 2, cql = lane & 3;

    uint32_t aoff[4], boff[2];
#pragma unroll
    for (int mt = 0; mt < 4; mt++)
        aoff[mt] = ((m_base + mt * 16 + (lane & 15)) * LDA + (lane >> 4) * 8) * 2;
#pragma unroll
    for (int p = 0; p < 2; p++) {
        int rowb = n_base + p * 16 + ((lane >> 4) & 1) * 8 + (lane & 7);
        boff[p] = (rowb * LDB + ((lane >> 3) & 1) * 8) * 2;
    }

    load_A(0, 0);
    load_A(1, BK);
    load_A(2, 2 * BK);

    for (int kt = 0; kt < ktiles; kt++) {
        const int rem = ktiles - 1 - kt;
        if (rem >= 2) CP_WAIT(2);
        else if (rem == 1) CP_WAIT(1);
        else CP_WAIT(0);
        __syncthreads();
        if (kt + 3 < ktiles) load_A((kt + 3) % STG, (kt + 3) * BK);

        const int s = kt % STG;
#pragma unroll
        for (int k0 = 0; k0 < BK; k0 += 16) {
            uint32_t af[4][4], bf[4][2];
            const uint32_t ab = a_base + s * ABUF + k0 * 2;
            const uint32_t bb = b_base + (kt * BK + k0) * 2;
#pragma unroll
            for (int mt = 0; mt < 4; mt++)
                ldsm_x4(af[mt][0], af[mt][1], af[mt][2], af[mt][3], ab + aoff[mt]);
#pragma unroll
            for (int p = 0; p < 2; p++)
                ldsm_x4(bf[2 * p][0], bf[2 * p][1], bf[2 * p + 1][0],
                        bf[2 * p + 1][1], bb + boff[p]);
#pragma unroll
            for (int mt = 0; mt < 4; mt++)
#pragma unroll
                for (int nt = 0; nt < 4; nt++)
                    mma_f16(acc[mt][nt], af[mt][0], af[mt][1], af[mt][2],
                            af[mt][3], bf[nt][0], bf[nt][1]);
        }
    }

#pragma unroll
    for (int mt = 0; mt < 4; mt++) {
#pragma unroll
        for (int half = 0; half < 2; half++) {
            int row = m0g + m_base + mt * 16 + rql + half * 8;
            if (row >= M) continue;
#pragma unroll
            for (int nt = 0; nt < 4; nt++) {
                int col = n_base + nt * 8 + cql * 2;
                float2 v;
                v.x = fmaxf(acc[mt][nt][half * 2 + 0], 0.f);
                v.y = fmaxf(acc[mt][nt][half * 2 + 1], 0.f);
                if (outh) {
                    *(__half2*)(Ch + (size_t)row * ldc + col) =
                        __floats2half2_rn(v.x, v.y);
                } else {
                    *(float2*)(Cf + (size_t)row * ldc + col) = v;
                }
            }
        }
    }
}

// ----------------- merged gather-max pools (fp16, one launch) ---------------
template<int NB>
__device__ __forceinline__ void pool_body(const __half* __restrict__ src,
                                          const int* __restrict__ idx,
                                          __half* __restrict__ dst,
                                          int* sidx)
{
    if (threadIdx.x < NB) sidx[threadIdx.x] = idx[threadIdx.x];
    __syncthreads();
    int c = threadIdx.x * 8;
    __half2 m0 = __float2half2_rn(0.f), m1 = m0, m2 = m0, m3 = m0;
#pragma unroll
    for (int j = 0; j < NB; j++) {
        uint4 v = *(const uint4*)(src + (size_t)sidx[j] * HIDW + c);
        const __half2* h = (const __half2*)&v;
        m0 = __hmax2(m0, h[0]);
        m1 = __hmax2(m1, h[1]);
        m2 = __hmax2(m2, h[2]);
        m3 = __hmax2(m3, h[3]);
    }
    __half2 r[4] = { m0, m1, m2, m3 };
    *(uint4*)(dst + c) = *(uint4*)r;
}

__global__ void k_pool_all(const __half* __restrict__ H)
{
    __shared__ int sidx[NS_A];
    int g = blockIdx.x;
    if (g < 2 * N1)
        pool_body<NS_A>(H, g_s2 + (size_t)g * NS_A, g_pool1 + (size_t)g * HIDW, sidx);
    else {
        g -= 2 * N1;
        pool_body<NS_B>(H, g_s1 + (size_t)g * NS_B, g_pool0 + (size_t)g * HIDW, sidx);
    }
}

// --------------------- segmented max (fp32, consecutive) --------------------
template<int NB>
__global__ void k_poolmax_f(const float* __restrict__ src, float* __restrict__ dst)
{
    int g = blockIdx.x;
    int c = threadIdx.x * 4;
    float4 m = make_float4(-1e30f, -1e30f, -1e30f, -1e30f);
#pragma unroll
    for (int j = 0; j < NB; j++) {
        const float4 v = *(const float4*)(src + (size_t)(g * NB + j) * HIDW + c);
        m.x = fmaxf(m.x, v.x);
        m.y = fmaxf(m.y, v.y);
        m.z = fmaxf(m.z, v.z);
        m.w = fmaxf(m.w, v.w);
    }
    *(float4*)(dst + (size_t)g * HIDW + c) = m;
}

// -------------------- layer-1 combine + L2 normalize ------------------------
__global__ void k_final(const float* __restrict__ y0, const float* __restrict__ p2,
                        const float* __restrict__ Ws1, const float* __restrict__ Wn1,
                        float* __restrict__ out)
{
    int n = blockIdx.x;
    __shared__ float ss[256];
    __shared__ float sp[512];
    __shared__ float red[256];
    int tid = threadIdx.x;
    ss[tid] = y0[(size_t)n * 256 + tid];
    sp[tid] = p2[(size_t)n * 512 + tid];
    sp[256 + tid] = p2[(size_t)n * 512 + 256 + tid];
    __syncthreads();

    float acc = 0.f;
    if (tid < 128) {
#pragma unroll 8
        for (int k = 0; k < 256; k++) acc += ss[k] * Ws1[k * 128 + tid];
    } else {
        int c = tid - 128;
#pragma unroll 8
        for (int k = 0; k < 512; k++) acc += sp[k] * Wn1[k * 128 + c];
    }
    red[tid] = acc * acc;
    __syncthreads();
    for (int s = 128; s > 0; s >>= 1) {
        if (tid < s) red[tid] += red[tid + s];
        __syncthreads();
    }
    float inv = 1.f / fmaxf(sqrtf(red[0]), 1e-12f);
    out[(size_t)n * 256 + tid] = acc * inv;
}

// ------------------------------- launcher -----------------------------------
#define SMEM_W64 ((256 * (256 + 8) + 4 * 128 * 40) * 2)    // 176128
#define SMEM_L0  ((128 * (512 + 8) + 4 * 128 * 40) * 2)    // 174080

extern "C" void kernel_launch(void* const* d_in, const int* in_sizes, int n_in,
                              void* d_out, int out_size)
{
    (void)in_sizes; (void)n_in; (void)out_size;
    const int*   b1   = (const int*)d_in[0];
    const int*   b2   = (const int*)d_in[1];
    const float* feat = (const float*)d_in[2];
    const int*   adj  = (const int*)d_in[3];
    const float* Wp0  = (const float*)d_in[4];
    const float* bp0  = (const float*)d_in[5];
    const float* Wn0  = (const float*)d_in[6];
    const float* Ws0  = (const float*)d_in[7];
    const float* Wp1  = (const float*)d_in[8];
    const float* bp1  = (const float*)d_in[9];
    const float* Wn1  = (const float*)d_in[10];
    const float* Ws1  = (const float*)d_in[11];
    float* out = (float*)d_out;

    int *s1, *s2, *b12;
    __half *featH, *H, *pool1, *pool0, *y1, *Wp0t, *Wn0t, *Ws0t, *Wp1t;
    float *y0, *T, *pool2;
    cudaGetSymbolAddress((void**)&s1,    g_s1);
    cudaGetSymbolAddress((void**)&s2,    g_s2);
    cudaGetSymbolAddress((void**)&b12,   g_b12);
    cudaGetSymbolAddress((void**)&featH, g_featH);
    cudaGetSymbolAddress((void**)&H,     g_H);
    cudaGetSymbolAddress((void**)&pool1, g_pool1);
    cudaGetSymbolAddress((void**)&pool0, g_pool0);
    cudaGetSymbolAddress((void**)&y1,    g_y1);
    cudaGetSymbolAddress((void**)&y0,    g_y0);
    cudaGetSymbolAddress((void**)&T,     g_T);
    cudaGetSymbolAddress((void**)&pool2, g_pool2);
    cudaGetSymbolAddress((void**)&Wp0t,  g_Wp0t);
    cudaGetSymbolAddress((void**)&Wn0t,  g_Wn0t);
    cudaGetSymbolAddress((void**)&Ws0t,  g_Ws0t);
    cudaGetSymbolAddress((void**)&Wp1t,  g_Wp1t);

    cudaFuncSetAttribute(k_gemm_w64<true>,
                         cudaFuncAttributeMaxDynamicSharedMemorySize, SMEM_W64);
    cudaFuncSetAttribute(k_gemm_w64<false>,
                         cudaFuncAttributeMaxDynamicSharedMemorySize, SMEM_W64);
    cudaFuncSetAttribute(k_gemm_l0,
                         cudaFuncAttributeMaxDynamicSharedMemorySize, SMEM_L0);

    // 0,1: sampling   2: prep   3: H GEMM (ncu profiles launch index 3)
    k_sample1<<<(2 * N1 + 255) / 256, 256>>>(b1, b2, adj);
    k_sample2<<<(2 * N2 + 255) / 256, 256>>>(adj);
    k_prep<<<352 + 12500, 256>>>(Wp0, Wn0, Ws0, Wp1, feat);

    // H_all = relu(featH @ W_pool0 + b)  [100000, 512] fp16 out
    k_gemm_w64<true><<<dim3((NN + 127) / 128, HIDW / 256), 256, SMEM_W64>>>(
        featH, NN, Wp0t, bp0, H, HIDW);

    // 4: both pools in one launch
    k_pool_all<<<2 * N1 + 2 * BATCH, 64>>>(H);

    // 5: all four layer-0 GEMMs in one launch (176 CTAs)
    k_gemm_l0<<<176, 256, SMEM_L0>>>(featH, s1, pool1, b12, pool0,
                                     Ws0t, Wn0t, y1, y0);

    // 6,7: layer-1 pool MLP + consecutive segmax
    k_gemm_w64<false><<<dim3(2 * N1 / 128, HIDW / 256), 256, SMEM_W64>>>(
        y1, 2 * N1, Wp1t, bp1, T, HIDW);
    k_poolmax_f<NS_B><<<2 * BATCH, 128>>>(T, pool2);

    // 8: final combine + L2 normalize (exact fp32)
    k_final<<<2 * BATCH, 256>>>(y0, pool2, Ws1, Wn1, out);
}

// round 16
// speedup vs baseline: 1.1773x; 1.1773x over previous
#include <cuda_runtime.h>
#include <cuda_fp16.h>
#include <cstdint>

// ---------------------------------------------------------------------------
// SampleAndAggregate (GraphSAGE, 2-layer maxpool)
// Round 16: revert R15 wide tile (occupancy loss beat ldsm savings).
// R14 config + persistent-CTA m-loop for H/T GEMMs: B slice loaded once per
// CTA, A pipeline streams across m-tiles (one fill/drain per CTA, not per tile).
// ---------------------------------------------------------------------------

#define BATCH 512
#define FEAT  256
#define HIDW  512
#define DOUT  128
#define DEG   128
#define NN    100000
#define NS_A  25
#define NS_B  10
#define N1    (BATCH*NS_B)     // 5120
#define N2    (N1*NS_A)        // 128000

// ------------------------- scratch (device globals) ------------------------
__device__ int    g_s1[2*N1];
__device__ int    g_s2[2*N2];
__device__ int    g_b12[2*BATCH];
__device__ __half g_featH[(size_t)NN*FEAT];
__device__ __half g_Wp0t[HIDW*FEAT];   // [512][256]
__device__ __half g_Wn0t[DOUT*HIDW];   // [128][512]
__device__ __half g_Ws0t[DOUT*FEAT];   // [128][256]
__device__ __half g_Wp1t[HIDW*2*DOUT]; // [512][256]
__device__ __half g_H[(size_t)NN*HIDW];
__device__ __half g_pool1[2*(size_t)N1*HIDW];
__device__ __half g_pool0[2*(size_t)BATCH*HIDW];
__device__ __half g_y1[2*(size_t)N1*2*DOUT];
__device__ float  g_y0[2*(size_t)BATCH*2*DOUT];
__device__ float  g_T[2*(size_t)N1*HIDW];
__device__ float  g_pool2[2*(size_t)BATCH*HIDW];

// ------------------------------- sampling ----------------------------------
__global__ void k_sample1(const int* __restrict__ b1, const int* __restrict__ b2,
                          const int* __restrict__ adj) {
    int i = blockIdx.x * blockDim.x + threadIdx.x;
    if (i >= 2 * N1) return;
    int t = i / N1, r = i % N1;
    int n = r / NS_B, j = r % NS_B;
    int node = (t ? b2 : b1)[n];
    if (j == 0) g_b12[t * BATCH + n] = node;
    g_s1[t * N1 + r] = adj[(size_t)node * DEG + j];
}
__global__ void k_sample2(const int* __restrict__ adj) {
    int i = blockIdx.x * blockDim.x + threadIdx.x;
    if (i >= 2 * N2) return;
    int t = i / N2, r = i % N2;
    int n = r / NS_A, j = r % NS_A;
    int parent = g_s1[t * N1 + n];
    g_s2[t * N2 + r] = adj[(size_t)parent * DEG + j];
}

// ----- merged prep: weight transpose+cvt (blocks 0..351) + feat cvt rest ----
__global__ void k_prep(const float* __restrict__ Wp0, const float* __restrict__ Wn0,
                       const float* __restrict__ Ws0, const float* __restrict__ Wp1,
                       const float* __restrict__ feat) {
    int b = blockIdx.x;
    int tid = threadIdx.x;
    if (b < 352) {
        __shared__ float t[32][33];
        int tx = tid & 31, ty = tid >> 5;
        const float* W; __half* out; int K, N;
        if (b < 128)      { W = Wp0; out = g_Wp0t; K = 256; N = 512; }
        else if (b < 192) { b -= 128; W = Wn0; out = g_Wn0t; K = 512; N = 128; }
        else if (b < 224) { b -= 192; W = Ws0; out = g_Ws0t; K = 256; N = 128; }
        else              { b -= 224; W = Wp1; out = g_Wp1t; K = 256; N = 512; }
        int tilesN = N / 32;
        int n0 = (b % tilesN) * 32, k0 = (b / tilesN) * 32;
        for (int i = ty; i < 32; i += 8)
            t[i][tx] = W[(size_t)(k0 + i) * N + n0 + tx];
        __syncthreads();
        for (int i = ty; i < 32; i += 8)
            out[(size_t)(n0 + i) * K + k0 + tx] = __float2half_rn(t[tx][i]);
    } else {
        size_t i = (size_t)(b - 352) * 256 + tid;
        const float4* src = (const float4*)feat + i * 2;
        float4 a = src[0], c = src[1];
        __half2 h[4] = { __floats2half2_rn(a.x, a.y), __floats2half2_rn(a.z, a.w),
                         __floats2half2_rn(c.x, c.y), __floats2half2_rn(c.z, c.w) };
        *((uint4*)g_featH + i) = *(uint4*)h;
    }
}

// ----------------------------- fp16 MMA helpers -----------------------------
__device__ __forceinline__ void mma_f16(float c[4], uint32_t a0, uint32_t a1,
                                        uint32_t a2, uint32_t a3,
                                        uint32_t b0, uint32_t b1) {
    asm volatile(
        "mma.sync.aligned.m16n8k16.row.col.f32.f16.f16.f32 "
        "{%0,%1,%2,%3}, {%4,%5,%6,%7}, {%8,%9}, {%0,%1,%2,%3};"
        : "+f"(c[0]), "+f"(c[1]), "+f"(c[2]), "+f"(c[3])
        : "r"(a0), "r"(a1), "r"(a2), "r"(a3), "r"(b0), "r"(b1));
}
__device__ __forceinline__ void ldsm_x4(uint32_t& r0, uint32_t& r1,
                                        uint32_t& r2, uint32_t& r3,
                                        uint32_t addr) {
    asm volatile("ldmatrix.sync.aligned.m8n8.x4.shared.b16 {%0,%1,%2,%3}, [%4];"
                 : "=r"(r0), "=r"(r1), "=r"(r2), "=r"(r3) : "r"(addr));
}
__device__ __forceinline__ void cp16(uint32_t dst, const void* src, uint32_t sz) {
    asm volatile("cp.async.cg.shared.global [%0], [%1], 16, %2;"
                 :: "r"(dst), "l"(src), "r"(sz) : "memory");
}
#define CP_COMMIT() asm volatile("cp.async.commit_group;" ::: "memory")
#define CP_WAIT(n)  asm volatile("cp.async.wait_group %0;" :: "n"(n) : "memory")

// ---------------------------------------------------------------------------
// Persistent B-resident GEMM: KT=256, BM=128, BN=128, warp tile 64x32, occ 2.
// grid.x = ncols(4) * nCTA_m;  n0g = (bid&3)*128;  m-tiles strided by grid/4.
// B slice loaded ONCE per CTA; A streams through a 4-stage cp.async pipeline
// whose chunk sequence runs ACROSS m-tiles (epilogue at each 8-chunk boundary).
// ---------------------------------------------------------------------------
template<bool OUTH>
__global__ __launch_bounds__(256, 2)
void k_gemm_pers(const __half* __restrict__ A, int M,
                 const __half* __restrict__ Bt,
                 const float* __restrict__ bias,
                 void* __restrict__ Cv, int ldc)
{
    constexpr int BM = 128, BK = 32, KT = 256, STG = 4;
    constexpr int LDA = BK + 8;                // 40 halves / A row
    constexpr int LDB = KT + 8;                // 264 halves / B row
    constexpr int KTILES = KT / BK;            // 8 chunks per m-tile
    constexpr uint32_t ABUF = BM * LDA * 2;
    extern __shared__ __align__(16) __half sm[];

    const int tid  = threadIdx.x;
    const int lane = tid & 31;
    const int warp = tid >> 5;
    const int wm = warp >> 2, wn = warp & 3;
    const int n0g = (blockIdx.x & 3) * 128;
    const int mt0 = blockIdx.x >> 2;
    const int mstride = gridDim.x >> 2;
    const int NMT = (M + BM - 1) / BM;

    const uint32_t b_base = (uint32_t)__cvta_generic_to_shared(sm);
    const uint32_t a_base = b_base + 128 * LDB * 2;

    // ---- load this CTA's B slice (128 x 256 fp16) once ----
    constexpr int BCH = 128 * (KT / 8) / 256;
#pragma unroll
    for (int i = 0; i < BCH; i++) {
        int f = tid + i * 256;
        int row = f / (KT / 8), u = f % (KT / 8);
        cp16(b_base + (row * LDB + u * 8) * 2,
             Bt + (size_t)(n0g + row) * KT + u * 8, 16u);
    }
    CP_COMMIT();

    // number of chunks this CTA processes (>=8 when it owns >=1 m-tile)
    const int nmt_own = (NMT > mt0) ? (NMT - mt0 + mstride - 1) / mstride : 0;
    const int nchunks = nmt_own * KTILES;
    if (nchunks == 0) return;

    float acc[4][4][4];
#pragma unroll
    for (int i = 0; i < 4; i++)
#pragma unroll
        for (int j = 0; j < 4; j++)
#pragma unroll
            for (int r = 0; r < 4; r++) acc[i][j][r] = 0.f;

    auto load_chunk = [&](int c) {
        const int s = c & 3;
        const int m0g = (mt0 + (c >> 3) * mstride) * BM;
        const int kk = (c & 7) * BK;
#pragma unroll
        for (int i = 0; i < 2; i++) {
            int f = tid + i * 256;
            int m = f >> 2, u = f & 3;
            int row = m0g + m;
            bool v = row < M;
            const __half* src = A;
            if (v) src = A + (size_t)row * KT + kk + u * 8;
            cp16(a_base + s * ABUF + (m * LDA + u * 8) * 2, src, v ? 16u : 0u);
        }
        CP_COMMIT();
    };

    const int m_base = wm * 64, n_base = wn * 32;
    const int rql = lane >> 2, cql = lane & 3;

    uint32_t aoff[4], boff[2];
#pragma unroll
    for (int mt = 0; mt < 4; mt++)
        aoff[mt] = ((m_base + mt * 16 + (lane & 15)) * LDA + (lane >> 4) * 8) * 2;
#pragma unroll
    for (int p = 0; p < 2; p++) {
        int rowb = n_base + p * 16 + ((lane >> 4) & 1) * 8 + (lane & 7);
        boff[p] = (rowb * LDB + ((lane >> 3) & 1) * 8) * 2;
    }

    load_chunk(0);
    load_chunk(1);
    load_chunk(2);

    for (int c = 0; c < nchunks; c++) {
        // commit order: B, s(c=0), s(1), s(2), then one per iteration.
        // wait(2) at iteration c guarantees stage c&3 (and B) complete.
        const int rem = nchunks - 1 - c;
        if (rem >= 2) CP_WAIT(2);
        else if (rem == 1) CP_WAIT(1);
        else CP_WAIT(0);
        __syncthreads();
        if (c + 3 < nchunks) load_chunk(c + 3);

        const int s = c & 3;
        const int kk = (c & 7) * BK;
#pragma unroll
        for (int k0 = 0; k0 < BK; k0 += 16) {
            uint32_t af[4][4], bf[4][2];
            const uint32_t ab = a_base + s * ABUF + k0 * 2;
            const uint32_t bb = b_base + (kk + k0) * 2;
#pragma unroll
            for (int mt = 0; mt < 4; mt++)
                ldsm_x4(af[mt][0], af[mt][1], af[mt][2], af[mt][3], ab + aoff[mt]);
#pragma unroll
            for (int p = 0; p < 2; p++)
                ldsm_x4(bf[2 * p][0], bf[2 * p][1], bf[2 * p + 1][0],
                        bf[2 * p + 1][1], bb + boff[p]);
#pragma unroll
            for (int mt = 0; mt < 4; mt++)
#pragma unroll
                for (int nt = 0; nt < 4; nt++)
                    mma_f16(acc[mt][nt], af[mt][0], af[mt][1], af[mt][2],
                            af[mt][3], bf[nt][0], bf[nt][1]);
        }

        // m-tile boundary: epilogue + reset accumulators
        if ((c & 7) == 7) {
            const int m0g = (mt0 + (c >> 3) * mstride) * BM;
#pragma unroll
            for (int mt = 0; mt < 4; mt++) {
#pragma unroll
                for (int half = 0; half < 2; half++) {
                    int row = m0g + m_base + mt * 16 + rql + half * 8;
                    if (row >= M) continue;
#pragma unroll
                    for (int nt = 0; nt < 4; nt++) {
                        int col = n0g + n_base + nt * 8 + cql * 2;
                        float2 v;
                        v.x = fmaxf(acc[mt][nt][half * 2 + 0] + bias[col],     0.f);
                        v.y = fmaxf(acc[mt][nt][half * 2 + 1] + bias[col + 1], 0.f);
                        if (OUTH) {
                            *(__half2*)((__half*)Cv + (size_t)row * ldc + col) =
                                __floats2half2_rn(v.x, v.y);
                        } else {
                            *(float2*)((float*)Cv + (size_t)row * ldc + col) = v;
                        }
                    }
                }
            }
#pragma unroll
            for (int i = 0; i < 4; i++)
#pragma unroll
                for (int j = 0; j < 4; j++)
#pragma unroll
                    for (int r = 0; r < 4; r++) acc[i][j][r] = 0.f;
        }
    }
}

// ---------------------------------------------------------------------------
// Merged layer-0 GEMM: all four combine GEMMs in one launch (176 CTAs).
// (unchanged from R14)
// ---------------------------------------------------------------------------
__global__ __launch_bounds__(256, 1)
void k_gemm_l0(const __half* __restrict__ featH, const int* __restrict__ s1,
               const __half* __restrict__ pool1, const int* __restrict__ b12,
               const __half* __restrict__ pool0,
               const __half* __restrict__ Ws0t, const __half* __restrict__ Wn0t,
               __half* __restrict__ y1, float* __restrict__ y0)
{
    constexpr int BM = 128, BK = 32, STG = 4;
    constexpr int LDA = BK + 8;
    constexpr uint32_t ABUF = BM * LDA * 2;
    extern __shared__ __align__(16) __half sm[];

    int b = blockIdx.x;
    const __half* A; const int* gidx = nullptr; const __half* Bt;
    int M, KT; bool outh;
    __half* Ch = nullptr; float* Cf = nullptr;
    if (b < 80)       { A = featH; gidx = s1;  Bt = Ws0t; M = 2*N1;    KT = 256; outh = true;  Ch = y1; }
    else if (b < 160) { b -= 80;  A = pool1;             Bt = Wn0t; M = 2*N1;    KT = 512; outh = true;  Ch = y1 + 128; }
    else if (b < 168) { b -= 160; A = featH; gidx = b12; Bt = Ws0t; M = 2*BATCH; KT = 256; outh = false; Cf = y0; }
    else              { b -= 168; A = pool0;             Bt = Wn0t; M = 2*BATCH; KT = 512; outh = false; Cf = y0 + 128; }
    const int ldc = 256;
    const int m0g = b * BM;
    const int LDB = KT + 8;
    const int ktiles = KT / BK;
    const int kt8 = KT / 8;

    const int tid  = threadIdx.x;
    const int lane = tid & 31;
    const int warp = tid >> 5;
    const int wm = warp >> 2, wn = warp & 3;

    const uint32_t b_base = (uint32_t)__cvta_generic_to_shared(sm);
    const uint32_t a_base = b_base + 128 * (512 + 8) * 2;

    const int bch = 128 * kt8 / 256;
    for (int i = 0; i < bch; i++) {
        int f = tid + i * 256;
        int row = f / kt8, u = f % kt8;
        cp16(b_base + (row * LDB + u * 8) * 2,
             Bt + (size_t)row * KT + u * 8, 16u);
    }
    CP_COMMIT();

    float acc[4][4][4];
#pragma unroll
    for (int i = 0; i < 4; i++)
#pragma unroll
        for (int j = 0; j < 4; j++)
#pragma unroll
            for (int r = 0; r < 4; r++) acc[i][j][r] = 0.f;

    auto load_A = [&](int s, int kk) {
#pragma unroll
        for (int i = 0; i < 2; i++) {
            int f = tid + i * 256;
            int m = f >> 2, u = f & 3;
            int row = m0g + m;
            bool v = row < M;
            const __half* src = A;
            if (v) {
                int r = gidx ? gidx[row] : row;
                src = A + (size_t)r * KT + kk + u * 8;
            }
            cp16(a_base + s * ABUF + (m * LDA + u * 8) * 2, src, v ? 16u : 0u);
        }
        CP_COMMIT();
    };

    const int m_base = wm * 64, n_base = wn * 32;
    const int rql = lane >> 2, cql = lane & 3;

    uint32_t aoff[4], boff[2];
#pragma unroll
    for (int mt = 0; mt < 4; mt++)
        aoff[mt] = ((m_base + mt * 16 + (lane & 15)) * LDA + (lane >> 4) * 8) * 2;
#pragma unroll
    for (int p = 0; p < 2; p++) {
        int rowb = n_base + p * 16 + ((lane >> 4) & 1) * 8 + (lane & 7);
        boff[p] = (rowb * LDB + ((lane >> 3) & 1) * 8) * 2;
    }

    load_A(0, 0);
    load_A(1, BK);
    load_A(2, 2 * BK);

    for (int kt = 0; kt < ktiles; kt++) {
        const int rem = ktiles - 1 - kt;
        if (rem >= 2) CP_WAIT(2);
        else if (rem == 1) CP_WAIT(1);
        else CP_WAIT(0);
        __syncthreads();
        if (kt + 3 < ktiles) load_A((kt + 3) % STG, (kt + 3) * BK);

        const int s = kt % STG;
#pragma unroll
        for (int k0 = 0; k0 < BK; k0 += 16) {
            uint32_t af[4][4], bf[4][2];
            const uint32_t ab = a_base + s * ABUF + k0 * 2;
            const uint32_t bb = b_base + (kt * BK + k0) * 2;
#pragma unroll
            for (int mt = 0; mt < 4; mt++)
                ldsm_x4(af[mt][0], af[mt][1], af[mt][2], af[mt][3], ab + aoff[mt]);
#pragma unroll
            for (int p = 0; p < 2; p++)
                ldsm_x4(bf[2 * p][0], bf[2 * p][1], bf[2 * p + 1][0],
                        bf[2 * p + 1][1], bb + boff[p]);
#pragma unroll
            for (int mt = 0; mt < 4; mt++)
#pragma unroll
                for (int nt = 0; nt < 4; nt++)
                    mma_f16(acc[mt][nt], af[mt][0], af[mt][1], af[mt][2],
                            af[mt][3], bf[nt][0], bf[nt][1]);
        }
    }

#pragma unroll
    for (int mt = 0; mt < 4; mt++) {
#pragma unroll
        for (int half = 0; half < 2; half++) {
            int row = m0g + m_base + mt * 16 + rql + half * 8;
            if (row >= M) continue;
#pragma unroll
            for (int nt = 0; nt < 4; nt++) {
                int col = n_base + nt * 8 + cql * 2;
                float2 v;
                v.x = fmaxf(acc[mt][nt][half * 2 + 0], 0.f);
                v.y = fmaxf(acc[mt][nt][half * 2 + 1], 0.f);
                if (outh) {
                    *(__half2*)(Ch + (size_t)row * ldc + col) =
                        __floats2half2_rn(v.x, v.y);
                } else {
                    *(float2*)(Cf + (size_t)row * ldc + col) = v;
                }
            }
        }
    }
}

// ----------------- merged gather-max pools (fp16, one launch) ---------------
template<int NB>
__device__ __forceinline__ void pool_body(const __half* __restrict__ src,
                                          const int* __restrict__ idx,
                                          __half* __restrict__ dst,
                                          int* sidx)
{
    if (threadIdx.x < NB) sidx[threadIdx.x] = idx[threadIdx.x];
    __syncthreads();
    int c = threadIdx.x * 8;
    __half2 m0 = __float2half2_rn(0.f), m1 = m0, m2 = m0, m3 = m0;
#pragma unroll
    for (int j = 0; j < NB; j++) {
        uint4 v = *(const uint4*)(src + (size_t)sidx[j] * HIDW + c);
        const __half2* h = (const __half2*)&v;
        m0 = __hmax2(m0, h[0]);
        m1 = __hmax2(m1, h[1]);
        m2 = __hmax2(m2, h[2]);
        m3 = __hmax2(m3, h[3]);
    }
    __half2 r[4] = { m0, m1, m2, m3 };
    *(uint4*)(dst + c) = *(uint4*)r;
}

__global__ void k_pool_all(const __half* __restrict__ H)
{
    __shared__ int sidx[NS_A];
    int g = blockIdx.x;
    if (g < 2 * N1)
        pool_body<NS_A>(H, g_s2 + (size_t)g * NS_A, g_pool1 + (size_t)g * HIDW, sidx);
    else {
        g -= 2 * N1;
        pool_body<NS_B>(H, g_s1 + (size_t)g * NS_B, g_pool0 + (size_t)g * HIDW, sidx);
    }
}

// --------------------- segmented max (fp32, consecutive) --------------------
template<int NB>
__global__ void k_poolmax_f(const float* __restrict__ src, float* __restrict__ dst)
{
    int g = blockIdx.x;
    int c = threadIdx.x * 4;
    float4 m = make_float4(-1e30f, -1e30f, -1e30f, -1e30f);
#pragma unroll
    for (int j = 0; j < NB; j++) {
        const float4 v = *(const float4*)(src + (size_t)(g * NB + j) * HIDW + c);
        m.x = fmaxf(m.x, v.x);
        m.y = fmaxf(m.y, v.y);
        m.z = fmaxf(m.z, v.z);
        m.w = fmaxf(m.w, v.w);
    }
    *(float4*)(dst + (size_t)g * HIDW + c) = m;
}

// -------------------- layer-1 combine + L2 normalize ------------------------
__global__ void k_final(const float* __restrict__ y0, const float* __restrict__ p2,
                        const float* __restrict__ Ws1, const float* __restrict__ Wn1,
                        float* __restrict__ out)
{
    int n = blockIdx.x;
    __shared__ float ss[256];
    __shared__ float sp[512];
    __shared__ float red[256];
    int tid = threadIdx.x;
    ss[tid] = y0[(size_t)n * 256 + tid];
    sp[tid] = p2[(size_t)n * 512 + tid];
    sp[256 + tid] = p2[(size_t)n * 512 + 256 + tid];
    __syncthreads();

    float acc = 0.f;
    if (tid < 128) {
#pragma unroll 8
        for (int k = 0; k < 256; k++) acc += ss[k] * Ws1[k * 128 + tid];
    } else {
        int c = tid - 128;
#pragma unroll 8
        for (int k = 0; k < 512; k++) acc += sp[k] * Wn1[k * 128 + c];
    }
    red[tid] = acc * acc;
    __syncthreads();
    for (int s = 128; s > 0; s >>= 1) {
        if (tid < s) red[tid] += red[tid + s];
        __syncthreads();
    }
    float inv = 1.f / fmaxf(sqrtf(red[0]), 1e-12f);
    out[(size_t)n * 256 + tid] = acc * inv;
}

// ------------------------------- launcher -----------------------------------
#define SMEM_PERS ((128 * (256 + 8) + 4 * 128 * 40) * 2)   // 108544
#define SMEM_L0   ((128 * (512 + 8) + 4 * 128 * 40) * 2)   // 174080

extern "C" void kernel_launch(void* const* d_in, const int* in_sizes, int n_in,
                              void* d_out, int out_size)
{
    (void)in_sizes; (void)n_in; (void)out_size;
    const int*   b1   = (const int*)d_in[0];
    const int*   b2   = (const int*)d_in[1];
    const float* feat = (const float*)d_in[2];
    const int*   adj  = (const int*)d_in[3];
    const float* Wp0  = (const float*)d_in[4];
    const float* bp0  = (const float*)d_in[5];
    const float* Wn0  = (const float*)d_in[6];
    const float* Ws0  = (const float*)d_in[7];
    const float* Wp1  = (const float*)d_in[8];
    const float* bp1  = (const float*)d_in[9];
    const float* Wn1  = (const float*)d_in[10];
    const float* Ws1  = (const float*)d_in[11];
    float* out = (float*)d_out;

    int *s1, *s2, *b12;
    __half *featH, *H, *pool1, *pool0, *y1, *Wp0t, *Wn0t, *Ws0t, *Wp1t;
    float *y0, *T, *pool2;
    cudaGetSymbolAddress((void**)&s1,    g_s1);
    cudaGetSymbolAddress((void**)&s2,    g_s2);
    cudaGetSymbolAddress((void**)&b12,   g_b12);
    cudaGetSymbolAddress((void**)&featH, g_featH);
    cudaGetSymbolAddress((void**)&H,     g_H);
    cudaGetSymbolAddress((void**)&pool1, g_pool1);
    cudaGetSymbolAddress((void**)&pool0, g_pool0);
    cudaGetSymbolAddress((void**)&y1,    g_y1);
    cudaGetSymbolAddress((void**)&y0,    g_y0);
    cudaGetSymbolAddress((void**)&T,     g_T);
    cudaGetSymbolAddress((void**)&pool2, g_pool2);
    cudaGetSymbolAddress((void**)&Wp0t,  g_Wp0t);
    cudaGetSymbolAddress((void**)&Wn0t,  g_Wn0t);
    cudaGetSymbolAddress((void**)&Ws0t,  g_Ws0t);
    cudaGetSymbolAddress((void**)&Wp1t,  g_Wp1t);

    cudaFuncSetAttribute(k_gemm_pers<true>,
                         cudaFuncAttributeMaxDynamicSharedMemorySize, SMEM_PERS);
    cudaFuncSetAttribute(k_gemm_pers<false>,
                         cudaFuncAttributeMaxDynamicSharedMemorySize, SMEM_PERS);
    cudaFuncSetAttribute(k_gemm_l0,
                         cudaFuncAttributeMaxDynamicSharedMemorySize, SMEM_L0);

    // 0,1: sampling   2: prep   3: H GEMM (ncu profiles launch index 3)
    k_sample1<<<(2 * N1 + 255) / 256, 256>>>(b1, b2, adj);
    k_sample2<<<(2 * N2 + 255) / 256, 256>>>(adj);
    k_prep<<<352 + 12500, 256>>>(Wp0, Wn0, Ws0, Wp1, feat);

    // H_all = relu(featH @ W_pool0 + b) [100000,512] fp16; persistent 592 CTAs
    k_gemm_pers<true><<<592, 256, SMEM_PERS>>>(featH, NN, Wp0t, bp0, H, HIDW);

    // 4: both pools in one launch
    k_pool_all<<<2 * N1 + 2 * BATCH, 64>>>(H);

    // 5: all four layer-0 GEMMs in one launch (176 CTAs)
    k_gemm_l0<<<176, 256, SMEM_L0>>>(featH, s1, pool1, b12, pool0,
                                     Ws0t, Wn0t, y1, y0);

    // 6,7: layer-1 pool MLP (persistent, 320 CTAs) + consecutive segmax
    k_gemm_pers<false><<<320, 256, SMEM_PERS>>>(y1, 2 * N1, Wp1t, bp1, T, HIDW);
    k_poolmax_f<NS_B><<<2 * BATCH, 128>>>(T, pool2);

    // 8: final combine + L2 normalize (exact fp32)
    k_final<<<2 * BATCH, 256>>>(y0, pool2, Ws1, Wn1, out);
}

// round 17
// speedup vs baseline: 1.2021x; 1.0210x over previous
#include <cuda_runtime.h>
#include <cuda_fp16.h>
#include <cstdint>

// ---------------------------------------------------------------------------
// SampleAndAggregate (GraphSAGE, 2-layer maxpool)
// Round 17: R16 + l0 GEMM converted to streamed-A+B 3-stage pipeline
//           (61.4 KB smem -> occupancy 2 -> 176 CTAs in ONE wave; the old
//           B-resident l0 needed 174 KB -> occ 1 -> 2 waves).
// ---------------------------------------------------------------------------

#define BATCH 512
#define FEAT  256
#define HIDW  512
#define DOUT  128
#define DEG   128
#define NN    100000
#define NS_A  25
#define NS_B  10
#define N1    (BATCH*NS_B)     // 5120
#define N2    (N1*NS_A)        // 128000

// ------------------------- scratch (device globals) ------------------------
__device__ int    g_s1[2*N1];
__device__ int    g_s2[2*N2];
__device__ int    g_b12[2*BATCH];
__device__ __half g_featH[(size_t)NN*FEAT];
__device__ __half g_Wp0t[HIDW*FEAT];   // [512][256]
__device__ __half g_Wn0t[DOUT*HIDW];   // [128][512]
__device__ __half g_Ws0t[DOUT*FEAT];   // [128][256]
__device__ __half g_Wp1t[HIDW*2*DOUT]; // [512][256]
__device__ __half g_H[(size_t)NN*HIDW];
__device__ __half g_pool1[2*(size_t)N1*HIDW];
__device__ __half g_pool0[2*(size_t)BATCH*HIDW];
__device__ __half g_y1[2*(size_t)N1*2*DOUT];
__device__ float  g_y0[2*(size_t)BATCH*2*DOUT];
__device__ float  g_T[2*(size_t)N1*HIDW];
__device__ float  g_pool2[2*(size_t)BATCH*HIDW];

// ------------------------------- sampling ----------------------------------
__global__ void k_sample1(const int* __restrict__ b1, const int* __restrict__ b2,
                          const int* __restrict__ adj) {
    int i = blockIdx.x * blockDim.x + threadIdx.x;
    if (i >= 2 * N1) return;
    int t = i / N1, r = i % N1;
    int n = r / NS_B, j = r % NS_B;
    int node = (t ? b2 : b1)[n];
    if (j == 0) g_b12[t * BATCH + n] = node;
    g_s1[t * N1 + r] = adj[(size_t)node * DEG + j];
}
__global__ void k_sample2(const int* __restrict__ adj) {
    int i = blockIdx.x * blockDim.x + threadIdx.x;
    if (i >= 2 * N2) return;
    int t = i / N2, r = i % N2;
    int n = r / NS_A, j = r % NS_A;
    int parent = g_s1[t * N1 + n];
    g_s2[t * N2 + r] = adj[(size_t)parent * DEG + j];
}

// ----- merged prep: weight transpose+cvt (blocks 0..351) + feat cvt rest ----
__global__ void k_prep(const float* __restrict__ Wp0, const float* __restrict__ Wn0,
                       const float* __restrict__ Ws0, const float* __restrict__ Wp1,
                       const float* __restrict__ feat) {
    int b = blockIdx.x;
    int tid = threadIdx.x;
    if (b < 352) {
        __shared__ float t[32][33];
        int tx = tid & 31, ty = tid >> 5;
        const float* W; __half* out; int K, N;
        if (b < 128)      { W = Wp0; out = g_Wp0t; K = 256; N = 512; }
        else if (b < 192) { b -= 128; W = Wn0; out = g_Wn0t; K = 512; N = 128; }
        else if (b < 224) { b -= 192; W = Ws0; out = g_Ws0t; K = 256; N = 128; }
        else              { b -= 224; W = Wp1; out = g_Wp1t; K = 256; N = 512; }
        int tilesN = N / 32;
        int n0 = (b % tilesN) * 32, k0 = (b / tilesN) * 32;
        for (int i = ty; i < 32; i += 8)
            t[i][tx] = W[(size_t)(k0 + i) * N + n0 + tx];
        __syncthreads();
        for (int i = ty; i < 32; i += 8)
            out[(size_t)(n0 + i) * K + k0 + tx] = __float2half_rn(t[tx][i]);
    } else {
        size_t i = (size_t)(b - 352) * 256 + tid;
        const float4* src = (const float4*)feat + i * 2;
        float4 a = src[0], c = src[1];
        __half2 h[4] = { __floats2half2_rn(a.x, a.y), __floats2half2_rn(a.z, a.w),
                         __floats2half2_rn(c.x, c.y), __floats2half2_rn(c.z, c.w) };
        *((uint4*)g_featH + i) = *(uint4*)h;
    }
}

// ----------------------------- fp16 MMA helpers -----------------------------
__device__ __forceinline__ void mma_f16(float c[4], uint32_t a0, uint32_t a1,
                                        uint32_t a2, uint32_t a3,
                                        uint32_t b0, uint32_t b1) {
    asm volatile(
        "mma.sync.aligned.m16n8k16.row.col.f32.f16.f16.f32 "
        "{%0,%1,%2,%3}, {%4,%5,%6,%7}, {%8,%9}, {%0,%1,%2,%3};"
        : "+f"(c[0]), "+f"(c[1]), "+f"(c[2]), "+f"(c[3])
        : "r"(a0), "r"(a1), "r"(a2), "r"(a3), "r"(b0), "r"(b1));
}
__device__ __forceinline__ void ldsm_x4(uint32_t& r0, uint32_t& r1,
                                        uint32_t& r2, uint32_t& r3,
                                        uint32_t addr) {
    asm volatile("ldmatrix.sync.aligned.m8n8.x4.shared.b16 {%0,%1,%2,%3}, [%4];"
                 : "=r"(r0), "=r"(r1), "=r"(r2), "=r"(r3) : "r"(addr));
}
__device__ __forceinline__ void cp16(uint32_t dst, const void* src, uint32_t sz) {
    asm volatile("cp.async.cg.shared.global [%0], [%1], 16, %2;"
                 :: "r"(dst), "l"(src), "r"(sz) : "memory");
}
#define CP_COMMIT() asm volatile("cp.async.commit_group;" ::: "memory")
#define CP_WAIT(n)  asm volatile("cp.async.wait_group %0;" :: "n"(n) : "memory")

// ---------------------------------------------------------------------------
// Persistent B-resident GEMM: KT=256, BM=128, BN=128, warp tile 64x32, occ 2.
// (unchanged from R16 — measured 117.9us, tensor 41.7%)
// ---------------------------------------------------------------------------
template<bool OUTH>
__global__ __launch_bounds__(256, 2)
void k_gemm_pers(const __half* __restrict__ A, int M,
                 const __half* __restrict__ Bt,
                 const float* __restrict__ bias,
                 void* __restrict__ Cv, int ldc)
{
    constexpr int BM = 128, BK = 32, KT = 256;
    constexpr int LDA = BK + 8;
    constexpr int LDB = KT + 8;
    constexpr int KTILES = KT / BK;
    constexpr uint32_t ABUF = BM * LDA * 2;
    extern __shared__ __align__(16) __half sm[];

    const int tid  = threadIdx.x;
    const int lane = tid & 31;
    const int warp = tid >> 5;
    const int wm = warp >> 2, wn = warp & 3;
    const int n0g = (blockIdx.x & 3) * 128;
    const int mt0 = blockIdx.x >> 2;
    const int mstride = gridDim.x >> 2;
    const int NMT = (M + BM - 1) / BM;

    const uint32_t b_base = (uint32_t)__cvta_generic_to_shared(sm);
    const uint32_t a_base = b_base + 128 * LDB * 2;

    constexpr int BCH = 128 * (KT / 8) / 256;
#pragma unroll
    for (int i = 0; i < BCH; i++) {
        int f = tid + i * 256;
        int row = f / (KT / 8), u = f % (KT / 8);
        cp16(b_base + (row * LDB + u * 8) * 2,
             Bt + (size_t)(n0g + row) * KT + u * 8, 16u);
    }
    CP_COMMIT();

    const int nmt_own = (NMT > mt0) ? (NMT - mt0 + mstride - 1) / mstride : 0;
    const int nchunks = nmt_own * KTILES;
    if (nchunks == 0) return;

    float acc[4][4][4];
#pragma unroll
    for (int i = 0; i < 4; i++)
#pragma unroll
        for (int j = 0; j < 4; j++)
#pragma unroll
            for (int r = 0; r < 4; r++) acc[i][j][r] = 0.f;

    auto load_chunk = [&](int c) {
        const int s = c & 3;
        const int m0g = (mt0 + (c >> 3) * mstride) * BM;
        const int kk = (c & 7) * BK;
#pragma unroll
        for (int i = 0; i < 2; i++) {
            int f = tid + i * 256;
            int m = f >> 2, u = f & 3;
            int row = m0g + m;
            bool v = row < M;
            const __half* src = A;
            if (v) src = A + (size_t)row * KT + kk + u * 8;
            cp16(a_base + s * ABUF + (m * LDA + u * 8) * 2, src, v ? 16u : 0u);
        }
        CP_COMMIT();
    };

    const int m_base = wm * 64, n_base = wn * 32;
    const int rql = lane >> 2, cql = lane & 3;

    uint32_t aoff[4], boff[2];
#pragma unroll
    for (int mt = 0; mt < 4; mt++)
        aoff[mt] = ((m_base + mt * 16 + (lane & 15)) * LDA + (lane >> 4) * 8) * 2;
#pragma unroll
    for (int p = 0; p < 2; p++) {
        int rowb = n_base + p * 16 + ((lane >> 4) & 1) * 8 + (lane & 7);
        boff[p] = (rowb * LDB + ((lane >> 3) & 1) * 8) * 2;
    }

    load_chunk(0);
    load_chunk(1);
    load_chunk(2);

    for (int c = 0; c < nchunks; c++) {
        const int rem = nchunks - 1 - c;
        if (rem >= 2) CP_WAIT(2);
        else if (rem == 1) CP_WAIT(1);
        else CP_WAIT(0);
        __syncthreads();
        if (c + 3 < nchunks) load_chunk(c + 3);

        const int s = c & 3;
        const int kk = (c & 7) * BK;
#pragma unroll
        for (int k0 = 0; k0 < BK; k0 += 16) {
            uint32_t af[4][4], bf[4][2];
            const uint32_t ab = a_base + s * ABUF + k0 * 2;
            const uint32_t bb = b_base + (kk + k0) * 2;
#pragma unroll
            for (int mt = 0; mt < 4; mt++)
                ldsm_x4(af[mt][0], af[mt][1], af[mt][2], af[mt][3], ab + aoff[mt]);
#pragma unroll
            for (int p = 0; p < 2; p++)
                ldsm_x4(bf[2 * p][0], bf[2 * p][1], bf[2 * p + 1][0],
                        bf[2 * p + 1][1], bb + boff[p]);
#pragma unroll
            for (int mt = 0; mt < 4; mt++)
#pragma unroll
                for (int nt = 0; nt < 4; nt++)
                    mma_f16(acc[mt][nt], af[mt][0], af[mt][1], af[mt][2],
                            af[mt][3], bf[nt][0], bf[nt][1]);
        }

        if ((c & 7) == 7) {
            const int m0g = (mt0 + (c >> 3) * mstride) * BM;
#pragma unroll
            for (int mt = 0; mt < 4; mt++) {
#pragma unroll
                for (int half = 0; half < 2; half++) {
                    int row = m0g + m_base + mt * 16 + rql + half * 8;
                    if (row >= M) continue;
#pragma unroll
                    for (int nt = 0; nt < 4; nt++) {
                        int col = n0g + n_base + nt * 8 + cql * 2;
                        float2 v;
                        v.x = fmaxf(acc[mt][nt][half * 2 + 0] + bias[col],     0.f);
                        v.y = fmaxf(acc[mt][nt][half * 2 + 1] + bias[col + 1], 0.f);
                        if (OUTH) {
                            *(__half2*)((__half*)Cv + (size_t)row * ldc + col) =
                                __floats2half2_rn(v.x, v.y);
                        } else {
                            *(float2*)((float*)Cv + (size_t)row * ldc + col) = v;
                        }
                    }
                }
            }
#pragma unroll
            for (int i = 0; i < 4; i++)
#pragma unroll
                for (int j = 0; j < 4; j++)
#pragma unroll
                    for (int r = 0; r < 4; r++) acc[i][j][r] = 0.f;
        }
    }
}

// ---------------------------------------------------------------------------
// Merged layer-0 GEMM, streamed A+B, 3-stage cp.async, 61.4 KB smem -> occ 2.
// 176 CTAs = one wave.  Per-block dispatch; runtime KT in {256,512}.
// ---------------------------------------------------------------------------
__global__ __launch_bounds__(256, 2)
void k_gemm_l0(const __half* __restrict__ featH, const int* __restrict__ s1,
               const __half* __restrict__ pool1, const int* __restrict__ b12,
               const __half* __restrict__ pool0,
               const __half* __restrict__ Ws0t, const __half* __restrict__ Wn0t,
               __half* __restrict__ y1, float* __restrict__ y0)
{
    constexpr int BK = 32, STG = 3;
    constexpr int LD = BK + 8;                     // 40 halves / row
    constexpr uint32_t BUF = 128 * LD * 2;         // 10240 B per A or B stage
    extern __shared__ __align__(16) __half sm[];

    int b = blockIdx.x;
    const __half* A; const int* gidx = nullptr; const __half* Bt;
    int M, KT; bool outh;
    __half* Ch = nullptr; float* Cf = nullptr;
    if (b < 80)       { A = featH; gidx = s1;  Bt = Ws0t; M = 2*N1;    KT = 256; outh = true;  Ch = y1; }
    else if (b < 160) { b -= 80;  A = pool1;             Bt = Wn0t; M = 2*N1;    KT = 512; outh = true;  Ch = y1 + 128; }
    else if (b < 168) { b -= 160; A = featH; gidx = b12; Bt = Ws0t; M = 2*BATCH; KT = 256; outh = false; Cf = y0; }
    else              { b -= 168; A = pool0;             Bt = Wn0t; M = 2*BATCH; KT = 512; outh = false; Cf = y0 + 128; }
    const int ldc = 256;
    const int m0g = b * 128;
    const int ktiles = KT / BK;

    const int tid  = threadIdx.x;
    const int lane = tid & 31;
    const int warp = tid >> 5;
    const int wm = warp >> 2, wn = warp & 3;

    const uint32_t base = (uint32_t)__cvta_generic_to_shared(sm);
    // stage layout: [A_s | B_s] pairs: stage s at base + s*2*BUF

    float acc[4][4][4];
#pragma unroll
    for (int i = 0; i < 4; i++)
#pragma unroll
        for (int j = 0; j < 4; j++)
#pragma unroll
            for (int r = 0; r < 4; r++) acc[i][j][r] = 0.f;

    auto load_stage = [&](int s, int kk) {
#pragma unroll
        for (int i = 0; i < 2; i++) {
            int f = tid + i * 256;
            int m = f >> 2, u = f & 3;
            int row = m0g + m;
            bool v = row < M;
            const __half* srcA = A;
            if (v) {
                int r = gidx ? gidx[row] : row;
                srcA = A + (size_t)r * KT + kk + u * 8;
            }
            cp16(base + s * 2 * BUF + (m * LD + u * 8) * 2, srcA, v ? 16u : 0u);
            cp16(base + s * 2 * BUF + BUF + (m * LD + u * 8) * 2,
                 Bt + (size_t)m * KT + kk + u * 8, 16u);
        }
        CP_COMMIT();
    };

    const int m_base = wm * 64, n_base = wn * 32;
    const int rql = lane >> 2, cql = lane & 3;

    uint32_t aoff[4], boff[2];
#pragma unroll
    for (int mt = 0; mt < 4; mt++)
        aoff[mt] = ((m_base + mt * 16 + (lane & 15)) * LD + (lane >> 4) * 8) * 2;
#pragma unroll
    for (int p = 0; p < 2; p++) {
        int rowb = n_base + p * 16 + ((lane >> 4) & 1) * 8 + (lane & 7);
        boff[p] = (rowb * LD + ((lane >> 3) & 1) * 8) * 2;
    }

    load_stage(0, 0);
    load_stage(1, BK);

    for (int kt = 0; kt < ktiles; kt++) {
        // pending groups at top: stage kt plus (kt+1) [and (kt+2) not yet issued].
        // wait(1) retires stage kt; tail drains fully.
        if (kt + 2 < ktiles) CP_WAIT(1);
        else CP_WAIT(0);
        __syncthreads();   // all warps done with iteration kt-1 -> its stage is reusable
        if (kt + 2 < ktiles) load_stage((kt + 2) % STG, (kt + 2) * BK);

        const int s = kt % STG;
#pragma unroll
        for (int k0 = 0; k0 < BK; k0 += 16) {
            uint32_t af[4][4], bf[4][2];
            const uint32_t ab = base + s * 2 * BUF + k0 * 2;
            const uint32_t bb = ab + BUF;
#pragma unroll
            for (int mt = 0; mt < 4; mt++)
                ldsm_x4(af[mt][0], af[mt][1], af[mt][2], af[mt][3], ab + aoff[mt]);
#pragma unroll
            for (int p = 0; p < 2; p++)
                ldsm_x4(bf[2 * p][0], bf[2 * p][1], bf[2 * p + 1][0],
                        bf[2 * p + 1][1], bb + boff[p]);
#pragma unroll
            for (int mt = 0; mt < 4; mt++)
#pragma unroll
                for (int nt = 0; nt < 4; nt++)
                    mma_f16(acc[mt][nt], af[mt][0], af[mt][1], af[mt][2],
                            af[mt][3], bf[nt][0], bf[nt][1]);
        }
    }

#pragma unroll
    for (int mt = 0; mt < 4; mt++) {
#pragma unroll
        for (int half = 0; half < 2; half++) {
            int row = m0g + m_base + mt * 16 + rql + half * 8;
            if (row >= M) continue;
#pragma unroll
            for (int nt = 0; nt < 4; nt++) {
                int col = n_base + nt * 8 + cql * 2;
                float2 v;
                v.x = fmaxf(acc[mt][nt][half * 2 + 0], 0.f);
                v.y = fmaxf(acc[mt][nt][half * 2 + 1], 0.f);
                if (outh) {
                    *(__half2*)(Ch + (size_t)row * ldc + col) =
                        __floats2half2_rn(v.x, v.y);
                } else {
                    *(float2*)(Cf + (size_t)row * ldc + col) = v;
                }
            }
        }
    }
}

// ----------------- merged gather-max pools (fp16, one launch) ---------------
template<int NB>
__device__ __forceinline__ void pool_body(const __half* __restrict__ src,
                                          const int* __restrict__ idx,
                                          __half* __restrict__ dst,
                                          int* sidx)
{
    if (threadIdx.x < NB) sidx[threadIdx.x] = idx[threadIdx.x];
    __syncthreads();
    int c = threadIdx.x * 8;
    __half2 m0 = __float2half2_rn(0.f), m1 = m0, m2 = m0, m3 = m0;
#pragma unroll
    for (int j = 0; j < NB; j++) {
        uint4 v = *(const uint4*)(src + (size_t)sidx[j] * HIDW + c);
        const __half2* h = (const __half2*)&v;
        m0 = __hmax2(m0, h[0]);
        m1 = __hmax2(m1, h[1]);
        m2 = __hmax2(m2, h[2]);
        m3 = __hmax2(m3, h[3]);
    }
    __half2 r[4] = { m0, m1, m2, m3 };
    *(uint4*)(dst + c) = *(uint4*)r;
}

__global__ void k_pool_all(const __half* __restrict__ H)
{
    __shared__ int sidx[NS_A];
    int g = blockIdx.x;
    if (g < 2 * N1)
        pool_body<NS_A>(H, g_s2 + (size_t)g * NS_A, g_pool1 + (size_t)g * HIDW, sidx);
    else {
        g -= 2 * N1;
        pool_body<NS_B>(H, g_s1 + (size_t)g * NS_B, g_pool0 + (size_t)g * HIDW, sidx);
    }
}

// --------------------- segmented max (fp32, consecutive) --------------------
template<int NB>
__global__ void k_poolmax_f(const float* __restrict__ src, float* __restrict__ dst)
{
    int g = blockIdx.x;
    int c = threadIdx.x * 4;
    float4 m = make_float4(-1e30f, -1e30f, -1e30f, -1e30f);
#pragma unroll
    for (int j = 0; j < NB; j++) {
        const float4 v = *(const float4*)(src + (size_t)(g * NB + j) * HIDW + c);
        m.x = fmaxf(m.x, v.x);
        m.y = fmaxf(m.y, v.y);
        m.z = fmaxf(m.z, v.z);
        m.w = fmaxf(m.w, v.w);
    }
    *(float4*)(dst + (size_t)g * HIDW + c) = m;
}

// -------------------- layer-1 combine + L2 normalize ------------------------
__global__ void k_final(const float* __restrict__ y0, const float* __restrict__ p2,
                        const float* __restrict__ Ws1, const float* __restrict__ Wn1,
                        float* __restrict__ out)
{
    int n = blockIdx.x;
    __shared__ float ss[256];
    __shared__ float sp[512];
    __shared__ float red[256];
    int tid = threadIdx.x;
    ss[tid] = y0[(size_t)n * 256 + tid];
    sp[tid] = p2[(size_t)n * 512 + tid];
    sp[256 + tid] = p2[(size_t)n * 512 + 256 + tid];
    __syncthreads();

    float acc = 0.f;
    if (tid < 128) {
#pragma unroll 8
        for (int k = 0; k < 256; k++) acc += ss[k] * Ws1[k * 128 + tid];
    } else {
        int c = tid - 128;
#pragma unroll 8
        for (int k = 0; k < 512; k++) acc += sp[k] * Wn1[k * 128 + c];
    }
    red[tid] = acc * acc;
    __syncthreads();
    for (int s = 128; s > 0; s >>= 1) {
        if (tid < s) red[tid] += red[tid + s];
        __syncthreads();
    }
    float inv = 1.f / fmaxf(sqrtf(red[0]), 1e-12f);
    out[(size_t)n * 256 + tid] = acc * inv;
}

// ------------------------------- launcher -----------------------------------
#define SMEM_PERS ((128 * (256 + 8) + 4 * 128 * 40) * 2)   // 108544
#define SMEM_L0   (3 * 2 * 128 * 40 * 2)                   // 61440

extern "C" void kernel_launch(void* const* d_in, const int* in_sizes, int n_in,
                              void* d_out, int out_size)
{
    (void)in_sizes; (void)n_in; (void)out_size;
    const int*   b1   = (const int*)d_in[0];
    const int*   b2   = (const int*)d_in[1];
    const float* feat = (const float*)d_in[2];
    const int*   adj  = (const int*)d_in[3];
    const float* Wp0  = (const float*)d_in[4];
    const float* bp0  = (const float*)d_in[5];
    const float* Wn0  = (const float*)d_in[6];
    const float* Ws0  = (const float*)d_in[7];
    const float* Wp1  = (const float*)d_in[8];
    const float* bp1  = (const float*)d_in[9];
    const float* Wn1  = (const float*)d_in[10];
    const float* Ws1  = (const float*)d_in[11];
    float* out = (float*)d_out;

    int *s1, *s2, *b12;
    __half *featH, *H, *pool1, *pool0, *y1, *Wp0t, *Wn0t, *Ws0t, *Wp1t;
    float *y0, *T, *pool2;
    cudaGetSymbolAddress((void**)&s1,    g_s1);
    cudaGetSymbolAddress((void**)&s2,    g_s2);
    cudaGetSymbolAddress((void**)&b12,   g_b12);
    cudaGetSymbolAddress((void**)&featH, g_featH);
    cudaGetSymbolAddress((void**)&H,     g_H);
    cudaGetSymbolAddress((void**)&pool1, g_pool1);
    cudaGetSymbolAddress((void**)&pool0, g_pool0);
    cudaGetSymbolAddress((void**)&y1,    g_y1);
    cudaGetSymbolAddress((void**)&y0,    g_y0);
    cudaGetSymbolAddress((void**)&T,     g_T);
    cudaGetSymbolAddress((void**)&pool2, g_pool2);
    cudaGetSymbolAddress((void**)&Wp0t,  g_Wp0t);
    cudaGetSymbolAddress((void**)&Wn0t,  g_Wn0t);
    cudaGetSymbolAddress((void**)&Ws0t,  g_Ws0t);
    cudaGetSymbolAddress((void**)&Wp1t,  g_Wp1t);

    cudaFuncSetAttribute(k_gemm_pers<true>,
                         cudaFuncAttributeMaxDynamicSharedMemorySize, SMEM_PERS);
    cudaFuncSetAttribute(k_gemm_pers<false>,
                         cudaFuncAttributeMaxDynamicSharedMemorySize, SMEM_PERS);
    cudaFuncSetAttribute(k_gemm_l0,
                         cudaFuncAttributeMaxDynamicSharedMemorySize, SMEM_L0);

    // 0,1: sampling   2: prep   3: H GEMM (ncu profiles launch index 3)
    k_sample1<<<(2 * N1 + 255) / 256, 256>>>(b1, b2, adj);
    k_sample2<<<(2 * N2 + 255) / 256, 256>>>(adj);
    k_prep<<<352 + 12500, 256>>>(Wp0, Wn0, Ws0, Wp1, feat);

    // H_all = relu(featH @ W_pool0 + b) [100000,512] fp16; persistent 592 CTAs
    k_gemm_pers<true><<<592, 256, SMEM_PERS>>>(featH, NN, Wp0t, bp0, H, HIDW);

    // 4: both pools in one launch
    k_pool_all<<<2 * N1 + 2 * BATCH, 64>>>(H);

    // 5: all four layer-0 GEMMs in one launch (176 CTAs, occ 2 -> one wave)
    k_gemm_l0<<<176, 256, SMEM_L0>>>(featH, s1, pool1, b12, pool0,
                                     Ws0t, Wn0t, y1, y0);

    // 6,7: layer-1 pool MLP (persistent, 320 CTAs) + consecutive segmax
    k_gemm_pers<false><<<320, 256, SMEM_PERS>>>(y1, 2 * N1, Wp1t, bp1, T, HIDW);
    k_poolmax_f<NS_B><<<2 * BATCH, 128>>>(T, pool2);

    // 8: final combine + L2 normalize (exact fp32)
    k_final<<<2 * BATCH, 256>>>(y0, pool2, Ws1, Wn1, out);
}